// round 16
// baseline (speedup 1.0000x reference)
#include <cuda_runtime.h>
#include <cuda_fp16.h>
#include <cstdint>

#define BB 4
#define SS 2048
#define DDIM 1024
#define HH 16
#define DKK 64
#define MTOT (BB*SS)   // 8192

// ---------------- scratch (static __device__, allocation-free) ----------------
__device__ __half g_xqh[(size_t)MTOT*DDIM];
__device__ __half g_xkh[(size_t)MTOT*DDIM];
__device__ __half g_xvh[(size_t)MTOT*DDIM];
__device__ __half g_Wh[4][(size_t)DDIM*DDIM];
__device__ __half g_Qh[(size_t)MTOT*DDIM];
__device__ __half g_Kh[(size_t)MTOT*DDIM];
__device__ __half g_Vh[(size_t)MTOT*DDIM];
__device__ __half g_Ah[(size_t)MTOT*DDIM];

// ---------------- helpers ----------------
__device__ __forceinline__ float ex2(float x) {
    float y;
    asm("ex2.approx.ftz.f32 %0, %1;" : "=f"(y) : "f"(x));
    return y;
}
__device__ __forceinline__ uint32_t packh2(float lo, float hi) {
    __half2 h = __floats2half2_rn(lo, hi);
    return *reinterpret_cast<uint32_t*>(&h);
}
__device__ __forceinline__ void cp16(uint32_t saddr, const void* g) {
    asm volatile("cp.async.cg.shared.global [%0], [%1], 16;" :: "r"(saddr), "l"(g));
}
__device__ __forceinline__ void cp4(uint32_t saddr, const void* g) {
    asm volatile("cp.async.ca.shared.global [%0], [%1], 4;" :: "r"(saddr), "l"(g));
}
__device__ __forceinline__ void cp_commit() {
    asm volatile("cp.async.commit_group;");
}
template <int N>
__device__ __forceinline__ void cp_wait() {
    asm volatile("cp.async.wait_group %0;" :: "n"(N));
}
__device__ __forceinline__ void ldsm4(uint32_t& r0, uint32_t& r1, uint32_t& r2, uint32_t& r3,
                                      uint32_t addr) {
    asm volatile("ldmatrix.sync.aligned.m8n8.x4.shared.b16 {%0,%1,%2,%3}, [%4];"
                 : "=r"(r0), "=r"(r1), "=r"(r2), "=r"(r3) : "r"(addr));
}
__device__ __forceinline__ void ldsm4t(uint32_t& r0, uint32_t& r1, uint32_t& r2, uint32_t& r3,
                                       uint32_t addr) {
    asm volatile("ldmatrix.sync.aligned.m8n8.x4.trans.shared.b16 {%0,%1,%2,%3}, [%4];"
                 : "=r"(r0), "=r"(r1), "=r"(r2), "=r"(r3) : "r"(addr));
}
// D(16x8,f32) += A(16x16,f16,row) * B(16x8,f16,col)
__device__ __forceinline__ void mma_f16(float c[4],
                                        uint32_t a0, uint32_t a1, uint32_t a2, uint32_t a3,
                                        uint32_t b0, uint32_t b1) {
    asm volatile(
        "mma.sync.aligned.m16n8k16.row.col.f32.f16.f16.f32 "
        "{%0,%1,%2,%3}, {%4,%5,%6,%7}, {%8,%9}, {%0,%1,%2,%3};"
        : "+f"(c[0]), "+f"(c[1]), "+f"(c[2]), "+f"(c[3])
        : "r"(a0), "r"(a1), "r"(a2), "r"(a3), "r"(b0), "r"(b1));
}

// ---------------- fused fp32 -> fp16 conversion: all 7 tensors, ONE launch ----------------
__global__ void f32to16_all(
    const float4* __restrict__ s0, const float4* __restrict__ s1, const float4* __restrict__ s2,
    const float4* __restrict__ s3, const float4* __restrict__ s4, const float4* __restrict__ s5,
    const float4* __restrict__ s6,
    uint4* __restrict__ d0, uint4* __restrict__ d1, uint4* __restrict__ d2,
    uint4* __restrict__ d3, uint4* __restrict__ d4, uint4* __restrict__ d5,
    uint4* __restrict__ d6,
    int nBig, int nSmall) {
    const int z = blockIdx.z;
    const float4* in;
    uint4* out;
    int n8;
    switch (z) {
        case 0: in = s0; out = d0; n8 = nBig; break;
        case 1: in = s1; out = d1; n8 = nBig; break;
        case 2: in = s2; out = d2; n8 = nBig; break;
        case 3: in = s3; out = d3; n8 = nSmall; break;
        case 4: in = s4; out = d4; n8 = nSmall; break;
        case 5: in = s5; out = d5; n8 = nSmall; break;
        default: in = s6; out = d6; n8 = nSmall; break;
    }
    int i = blockIdx.x * blockDim.x + threadIdx.x;
    const int stride = gridDim.x * blockDim.x;
#pragma unroll 2
    for (; i < n8; i += stride) {
        float4 v0 = in[2 * i];
        float4 v1 = in[2 * i + 1];
        uint4 o;
        o.x = packh2(v0.x, v0.y);
        o.y = packh2(v0.z, v0.w);
        o.z = packh2(v1.x, v1.y);
        o.w = packh2(v1.z, v1.w);
        out[i] = o;
    }
}

// ---------------- fp16 GEMM: C[m][n] = sum_k A[m][k] * W[n][k] (R13 proven) ----------------
#define GBM 128
#define GBN 128
#define GBKH 64
#define GSTH 72
#define GSTGH (GBM * GSTH)
#define GNS 3
#define GSMEM (2 * GNS * GSTGH * 2)           // 110592 B

__global__ __launch_bounds__(256, 2)
void gemm_h(const __half* __restrict__ A0, const __half* __restrict__ A1, const __half* __restrict__ A2,
            const __half* __restrict__ W0, const __half* __restrict__ W1, const __half* __restrict__ W2,
            float* __restrict__ C,
            __half* __restrict__ H0, __half* __restrict__ H1, __half* __restrict__ H2,
            int outHalf) {
    extern __shared__ __half hsm[];
    __half* Asm = hsm;
    __half* Bsm = hsm + GNS * GSTGH;

    const int z = blockIdx.z;
    const __half* A = (z == 0) ? A0 : (z == 1) ? A1 : A2;
    const __half* W = (z == 0) ? W0 : (z == 1) ? W1 : W2;
    __half* H = (z == 0) ? H0 : (z == 1) ? H1 : H2;

    const int m0 = blockIdx.y * GBM;
    const int n0 = blockIdx.x * GBN;
    const int tid = threadIdx.x;
    const int w = tid >> 5, lane = tid & 31;
    const int g = lane >> 2, tig = lane & 3;
    const int wm = (w >> 2) * 64;
    const int wn = (w & 3) * 32;

    const uint32_t sA = (uint32_t)__cvta_generic_to_shared(Asm);
    const uint32_t sB = (uint32_t)__cvta_generic_to_shared(Bsm);

    const int lane7 = lane & 7;
    const int a_ro = ((lane >> 3) & 1) * 8;
    const int a_kh = ((lane >> 4) & 1) * 8;
    const int b_no = ((lane >> 4) & 1) * 8;
    const int b_kh = ((lane >> 3) & 1) * 8;

    uint32_t aIdx[4];
#pragma unroll
    for (int mt = 0; mt < 4; mt++)
        aIdx[mt] = (uint32_t)(((wm + mt * 16 + a_ro + lane7) * GSTH + a_kh) * 2);
    uint32_t bIdx[2];
#pragma unroll
    for (int nb = 0; nb < 2; nb++)
        bIdx[nb] = (uint32_t)(((wn + nb * 16 + b_no + lane7) * GSTH + b_kh) * 2);

    float acc[4][4][4];
#pragma unroll
    for (int i = 0; i < 4; i++)
#pragma unroll
        for (int j = 0; j < 4; j++)
#pragma unroll
            for (int e = 0; e < 4; e++) acc[i][j][e] = 0.f;

    const int lr = tid >> 3;
    const int lc8 = (tid & 7) << 3;

    auto issue = [&](int st, int k0) {
#pragma unroll
        for (int it = 0; it < 4; it++) {
            int row = lr + it * 32;
            cp16(sA + (uint32_t)((st * GBM + row) * GSTH + lc8) * 2,
                 &A[(size_t)(m0 + row) * DDIM + k0 + lc8]);
            cp16(sB + (uint32_t)((st * GBN + row) * GSTH + lc8) * 2,
                 &W[(size_t)(n0 + row) * DDIM + k0 + lc8]);
        }
    };

    issue(0, 0); cp_commit();
    issue(1, GBKH); cp_commit();

    const int NKT = DDIM / GBKH;      // 16
    for (int kt = 0; kt < NKT; kt++) {
        if (kt < NKT - 1) cp_wait<1>(); else cp_wait<0>();
        __syncthreads();

        const int st = kt % GNS;
        const uint32_t stb = (uint32_t)(st * GSTGH * 2);

#pragma unroll
        for (int ks = 0; ks < 4; ks++) {
            const uint32_t ksB = (uint32_t)(ks * 32);
            uint32_t b[4][2];
            ldsm4(b[0][0], b[0][1], b[1][0], b[1][1], sB + stb + bIdx[0] + ksB);
            ldsm4(b[2][0], b[2][1], b[3][0], b[3][1], sB + stb + bIdx[1] + ksB);
#pragma unroll
            for (int mt = 0; mt < 4; mt++) {
                uint32_t a0, a1, a2, a3;
                ldsm4(a0, a1, a2, a3, sA + stb + aIdx[mt] + ksB);
#pragma unroll
                for (int nt = 0; nt < 4; nt++)
                    mma_f16(acc[mt][nt], a0, a1, a2, a3, b[nt][0], b[nt][1]);
            }
        }

        if (kt + 2 < NKT) {
            issue((kt + 2) % GNS, (kt + 2) * GBKH);
            cp_commit();
        }
    }

#pragma unroll
    for (int mt = 0; mt < 4; mt++) {
        int r0 = m0 + wm + mt * 16 + g;
#pragma unroll
        for (int nt = 0; nt < 4; nt++) {
            int col = n0 + wn + nt * 8 + 2 * tig;
            float v0 = acc[mt][nt][0], v1 = acc[mt][nt][1];
            float v2 = acc[mt][nt][2], v3 = acc[mt][nt][3];
            if (outHalf) {
                *reinterpret_cast<__half2*>(&H[(size_t)r0 * DDIM + col]) =
                    __floats2half2_rn(v0, v1);
                *reinterpret_cast<__half2*>(&H[(size_t)(r0 + 8) * DDIM + col]) =
                    __floats2half2_rn(v2, v3);
            } else {
                *reinterpret_cast<float2*>(&C[(size_t)r0 * DDIM + col]) = make_float2(v0, v1);
                *reinterpret_cast<float2*>(&C[(size_t)(r0 + 8) * DDIM + col]) = make_float2(v2, v3);
            }
        }
    }
}

// ---------------- flash attention: 128-row Q tile, 16 rows/warp, 2 CTAs/SM,
// ---------------- fragment-granular causal skipping ----------------
#define AQT 128
#define ATHR 256
#define HPH 72    // fp16 row stride (halves)
#define ASMEM ((2*64*HPH + 2*64*HPH + AQT*HPH) * 2 + 2 * 64 * 4)   // 55808 B

__global__ __launch_bounds__(ATHR, 2)
void attn_kernel(const __half* __restrict__ QH, const __half* __restrict__ KH,
                 const __half* __restrict__ VH,
                 const int* __restrict__ mask, __half* __restrict__ O) {
    extern __shared__ uint32_t smem_u[];
    __half* Kh0 = (__half*)smem_u;
    __half* Vh0 = Kh0 + 2 * 64 * HPH;
    __half* Qs  = Vh0 + 2 * 64 * HPH;              // AQT rows (Q staging, scaled)
    int* msk0 = (int*)(Qs + AQT * HPH);

    const int qi = gridDim.x - 1 - blockIdx.x;     // heavy tiles first
    const int bh = blockIdx.y;
    const int b = bh / HH, h = bh % HH;

    const int tid = threadIdx.x;
    const int w = tid >> 5, lane = tid & 31;
    const int g = lane >> 2, tig = lane & 3;
    const int wrow = w * 16;                       // 16 rows per warp

    const __half* Qb = QH + ((size_t)b * SS + (size_t)qi * AQT) * DDIM + h * DKK;
    const __half* Kb = KH + (size_t)b * SS * DDIM + h * DKK;
    const __half* Vb = VH + (size_t)b * SS * DDIM + h * DKK;
    __half* Ob = O + ((size_t)b * SS + (size_t)qi * AQT) * DDIM + h * DKK;

    const uint32_t sK = (uint32_t)__cvta_generic_to_shared(Kh0);
    const uint32_t sV = (uint32_t)__cvta_generic_to_shared(Vh0);
    const uint32_t sQ = (uint32_t)__cvta_generic_to_shared(Qs);
    const uint32_t sM = (uint32_t)__cvta_generic_to_shared(msk0);

    const int lane7 = lane & 7;
    const int a_ro = ((lane >> 3) & 1) * 8;
    const int a_kh = ((lane >> 4) & 1) * 8;
    const int b_no = ((lane >> 4) & 1) * 8;
    const int b_kh = ((lane >> 3) & 1) * 8;
    const int v_ro = lane & 15;
    const int v_co = (lane >> 4) * 8;

    const float qscale = 0.125f * 1.4426950408889634f;

    auto issueKV = [&](int st, int kt) {
        const __half* Kt = Kb + (size_t)kt * 64 * DDIM;
        const __half* Vt = Vb + (size_t)kt * 64 * DDIM;
#pragma unroll
        for (int t = 0; t < 2; t++) {
            int i = tid + t * ATHR;
            int r = i >> 3;
            int c8 = (i & 7) << 3;
            uint32_t off = (uint32_t)((st * 64 + r) * HPH + c8) * 2;
            cp16(sK + off, Kt + (size_t)r * DDIM + c8);
            cp16(sV + off, Vt + (size_t)r * DDIM + c8);
        }
        if (tid < 64) cp4(sM + (uint32_t)(st * 64 + tid) * 4, &mask[(size_t)b * SS + kt * 64 + tid]);
    };

    const int ktmax = 2 * qi + 1;
    issueKV(0, 0);
    cp_commit();

    // stage Q (AQT x 64 halves), scaled by qscale
#pragma unroll
    for (int t = 0; t < 4; t++) {
        int i = tid + t * ATHR;
        int r = i >> 3;
        int c8 = (i & 7) << 3;
        uint4 raw = *reinterpret_cast<const uint4*>(Qb + (size_t)r * DDIM + c8);
        const __half2* hp = reinterpret_cast<const __half2*>(&raw);
        uint4 outp;
        uint32_t* op = reinterpret_cast<uint32_t*>(&outp);
#pragma unroll
        for (int e = 0; e < 4; e++) {
            float2 f = __half22float2(hp[e]);
            op[e] = packh2(f.x * qscale, f.y * qscale);
        }
        *reinterpret_cast<uint4*>(&Qs[r * HPH + c8]) = outp;
    }
    __syncthreads();

    uint32_t qf[4][4];
    {
        const uint32_t base = sQ + (uint32_t)(((wrow + a_ro + lane7) * HPH + a_kh) * 2);
#pragma unroll
        for (int ks = 0; ks < 4; ks++)
            ldsm4(qf[ks][0], qf[ks][1], qf[ks][2], qf[ks][3],
                  base + (uint32_t)(ks * 32));
    }

    float mrow0 = -1e30f, mrow1 = -1e30f;
    float lrow0 = 0.f, lrow1 = 0.f;
    float o[8][4];
#pragma unroll
    for (int nt = 0; nt < 8; nt++)
#pragma unroll
        for (int e = 0; e < 4; e++) o[nt][e] = 0.f;

    const int rowmax = qi * AQT + wrow + 15;

    for (int kt = 0; kt <= ktmax; kt++) {
        const int cur = kt & 1;
        __syncthreads();
        if (kt < ktmax) {
            issueKV(cur ^ 1, kt + 1);
            cp_commit();
            cp_wait<1>();
        } else {
            cp_wait<0>();
        }
        __syncthreads();

        const uint32_t sKst = sK + (uint32_t)(cur * 64 * HPH * 2);
        const uint32_t vH0 = sV + (uint32_t)(cur * 64 * HPH * 2)
                           + (uint32_t)(v_ro * HPH + v_co) * 2;
        const int* msk = msk0 + cur * 64;

        if (kt * 64 > rowmax) continue;

        const int kbase = kt * 64;
        const int mvl0 = msk[lane], mvl1 = msk[32 + lane];
        const bool allvalid = __all_sync(0xffffffffu, (mvl0 != 0) && (mvl1 != 0));

        // S = Q @ K^T : 16x64 per warp, fp16 k16; skip fully-causally-masked fragments
        float s[8][4];
#pragma unroll
        for (int nt = 0; nt < 8; nt++)
            s[nt][0] = s[nt][1] = s[nt][2] = s[nt][3] = 0.f;

        const uint32_t kb0 = sKst + (uint32_t)(((b_no + lane7) * HPH + b_kh) * 2);
#pragma unroll
        for (int ks = 0; ks < 4; ks++) {
            const uint32_t ksB = (uint32_t)(ks * 32);
            uint32_t bf[8][2];
#pragma unroll
            for (int j = 0; j < 4; j++)
                if (kbase + j * 16 <= rowmax)      // warp-uniform causal skip (16-key granularity)
                    ldsm4(bf[2*j][0], bf[2*j][1], bf[2*j+1][0], bf[2*j+1][1],
                          kb0 + (uint32_t)(j * 16 * HPH * 2) + ksB);
#pragma unroll
            for (int nt = 0; nt < 8; nt++)
                if (kbase + nt * 8 <= rowmax)      // warp-uniform causal skip (8-key granularity)
                    mma_f16(s[nt], qf[ks][0], qf[ks][1], qf[ks][2], qf[ks][3],
                            bf[nt][0], bf[nt][1]);
        }

        // masking + online softmax; P packed to fp16 registers
        const int q0 = qi * AQT + wrow + g;
        const int q1 = q0 + 8;
        const bool needc = (kbase + 63 > qi * AQT + wrow);

        if (!allvalid) {
#pragma unroll
            for (int nt = 0; nt < 8; nt++) {
                int cl = nt * 8 + 2 * tig;
                int cg = kbase + cl;
                bool mv0 = (msk[cl] != 0);
                bool mv1 = (msk[cl + 1] != 0);
                if (!mv0 || (needc && cg > q0))     s[nt][0] = -1e30f;
                if (!mv1 || (needc && cg + 1 > q0)) s[nt][1] = -1e30f;
                if (!mv0 || (needc && cg > q1))     s[nt][2] = -1e30f;
                if (!mv1 || (needc && cg + 1 > q1)) s[nt][3] = -1e30f;
            }
        } else if (needc) {
#pragma unroll
            for (int nt = 0; nt < 8; nt++) {
                int cg = kbase + nt * 8 + 2 * tig;
                if (cg > q0)     s[nt][0] = -1e30f;
                if (cg + 1 > q0) s[nt][1] = -1e30f;
                if (cg > q1)     s[nt][2] = -1e30f;
                if (cg + 1 > q1) s[nt][3] = -1e30f;
            }
        }

        float rm0 = -1e30f, rm1 = -1e30f;
#pragma unroll
        for (int nt = 0; nt < 8; nt++) {
            rm0 = fmaxf(rm0, fmaxf(s[nt][0], s[nt][1]));
            rm1 = fmaxf(rm1, fmaxf(s[nt][2], s[nt][3]));
        }
        rm0 = fmaxf(rm0, __shfl_xor_sync(0xffffffffu, rm0, 1));
        rm0 = fmaxf(rm0, __shfl_xor_sync(0xffffffffu, rm0, 2));
        rm1 = fmaxf(rm1, __shfl_xor_sync(0xffffffffu, rm1, 1));
        rm1 = fmaxf(rm1, __shfl_xor_sync(0xffffffffu, rm1, 2));

        float mn0 = fmaxf(mrow0, rm0);
        float mn1 = fmaxf(mrow1, rm1);
        float al0 = ex2(mrow0 - mn0);
        float al1 = ex2(mrow1 - mn1);
        mrow0 = mn0; mrow1 = mn1;

        uint32_t ph[8][2];
        float rs0 = 0.f, rs1 = 0.f;
#pragma unroll
        for (int nt = 0; nt < 8; nt++) {
            float p0 = ex2(s[nt][0] - mn0);
            float p1 = ex2(s[nt][1] - mn0);
            float p2 = ex2(s[nt][2] - mn1);
            float p3 = ex2(s[nt][3] - mn1);
            rs0 += p0 + p1;
            rs1 += p2 + p3;
            ph[nt][0] = packh2(p0, p1);
            ph[nt][1] = packh2(p2, p3);
        }
        rs0 += __shfl_xor_sync(0xffffffffu, rs0, 1);
        rs0 += __shfl_xor_sync(0xffffffffu, rs0, 2);
        rs1 += __shfl_xor_sync(0xffffffffu, rs1, 1);
        rs1 += __shfl_xor_sync(0xffffffffu, rs1, 2);
        lrow0 = lrow0 * al0 + rs0;
        lrow1 = lrow1 * al1 + rs1;

#pragma unroll
        for (int nt = 0; nt < 8; nt++) {
            o[nt][0] *= al0; o[nt][1] *= al0;
            o[nt][2] *= al1; o[nt][3] *= al1;
        }

        // O += P @ V, fp16 m16n8k16; skip j-steps whose 16 keys are all causally masked (P==0)
#pragma unroll
        for (int j = 0; j < 4; j++) {
            if (kbase + j * 16 > rowmax) continue;   // warp-uniform
            const uint32_t jb = (uint32_t)(j * 16 * HPH * 2);
            uint32_t vf[8][2];
#pragma unroll
            for (int dgi = 0; dgi < 4; dgi++)
                ldsm4t(vf[2*dgi][0], vf[2*dgi][1], vf[2*dgi+1][0], vf[2*dgi+1][1],
                       vH0 + jb + (uint32_t)(dgi * 32));
            uint32_t a0 = ph[2*j][0],   a1 = ph[2*j][1];
            uint32_t a2 = ph[2*j+1][0], a3 = ph[2*j+1][1];
#pragma unroll
            for (int nt = 0; nt < 8; nt++)
                mma_f16(o[nt], a0, a1, a2, a3, vf[nt][0], vf[nt][1]);
        }
    }

    // normalize + store as fp16 (feeds the fp16 Wo GEMM)
    {
        float i0 = 1.f / lrow0;
        float i1 = 1.f / lrow1;
        int r0 = wrow + g;
#pragma unroll
        for (int nt = 0; nt < 8; nt++) {
            int cl = nt * 8 + 2 * tig;
            *reinterpret_cast<__half2*>(&Ob[(size_t)r0 * DDIM + cl]) =
                __floats2half2_rn(o[nt][0] * i0, o[nt][1] * i0);
            *reinterpret_cast<__half2*>(&Ob[(size_t)(r0 + 8) * DDIM + cl]) =
                __floats2half2_rn(o[nt][2] * i1, o[nt][3] * i1);
        }
    }
}

// ---------------- launch ----------------
extern "C" void kernel_launch(void* const* d_in, const int* in_sizes, int n_in,
                              void* d_out, int out_size) {
    const float* xq = (const float*)d_in[0];
    const float* xk = (const float*)d_in[1];
    const float* xv = (const float*)d_in[2];
    const int* mask = (const int*)d_in[3];
    const float* Wq = (const float*)d_in[4];
    const float* Wk = (const float*)d_in[5];
    const float* Wv = (const float*)d_in[6];
    const float* Wo = (const float*)d_in[7];
    float* out = (float*)d_out;

    __half *xqh, *xkh, *xvh, *Wh, *QHp, *KHp, *VHp, *AHp;
    cudaGetSymbolAddress((void**)&xqh, g_xqh);
    cudaGetSymbolAddress((void**)&xkh, g_xkh);
    cudaGetSymbolAddress((void**)&xvh, g_xvh);
    cudaGetSymbolAddress((void**)&Wh, g_Wh);
    cudaGetSymbolAddress((void**)&QHp, g_Qh);
    cudaGetSymbolAddress((void**)&KHp, g_Kh);
    cudaGetSymbolAddress((void**)&VHp, g_Vh);
    cudaGetSymbolAddress((void**)&AHp, g_Ah);

    __half* Wqh = Wh;
    __half* Wkh = Wh + (size_t)DDIM * DDIM;
    __half* Wvh = Wh + 2 * (size_t)DDIM * DDIM;
    __half* Woh = Wh + 3 * (size_t)DDIM * DDIM;

    cudaFuncSetAttribute(gemm_h, cudaFuncAttributeMaxDynamicSharedMemorySize, GSMEM);
    cudaFuncSetAttribute(attn_kernel, cudaFuncAttributeMaxDynamicSharedMemorySize, ASMEM);

    const int NX8 = (MTOT * DDIM) / 8;   // 1048576
    const int NW8 = (DDIM * DDIM) / 8;   // 131072

    f32to16_all<<<dim3(512, 1, 7), 256>>>(
        (const float4*)xq, (const float4*)xk, (const float4*)xv,
        (const float4*)Wq, (const float4*)Wk, (const float4*)Wv, (const float4*)Wo,
        (uint4*)xqh, (uint4*)xkh, (uint4*)xvh,
        (uint4*)Wqh, (uint4*)Wkh, (uint4*)Wvh, (uint4*)Woh,
        NX8, NW8);

    // fused QKV projections (fp16 in, fp16 out)
    gemm_h<<<dim3(DDIM / GBN, MTOT / GBM, 3), 256, GSMEM>>>(
        xqh, xkh, xvh, Wqh, Wkh, Wvh, nullptr, QHp, KHp, VHp, 1);

    attn_kernel<<<dim3(SS / AQT, BB * HH), ATHR, ASMEM>>>(QHp, KHp, VHp, mask, AHp);

    // output projection (fp16 in, fp32 out)
    gemm_h<<<dim3(DDIM / GBN, MTOT / GBM, 1), 256, GSMEM>>>(
        AHp, AHp, AHp, Woh, Woh, Woh, out, QHp, KHp, VHp, 0);
}

// round 17
// speedup vs baseline: 1.0063x; 1.0063x over previous
#include <cuda_runtime.h>
#include <cuda_fp16.h>
#include <cstdint>

#define BB 4
#define SS 2048
#define DDIM 1024
#define HH 16
#define DKK 64
#define MTOT (BB*SS)   // 8192

// ---------------- scratch (static __device__, allocation-free) ----------------
__device__ __half g_xqh[(size_t)MTOT*DDIM];
__device__ __half g_xkh[(size_t)MTOT*DDIM];
__device__ __half g_xvh[(size_t)MTOT*DDIM];
__device__ __half g_Wh[4][(size_t)DDIM*DDIM];
__device__ __half g_Qh[(size_t)MTOT*DDIM];
__device__ __half g_Kh[(size_t)MTOT*DDIM];
__device__ __half g_Vh[(size_t)MTOT*DDIM];
__device__ __half g_Ah[(size_t)MTOT*DDIM];

// ---------------- helpers ----------------
__device__ __forceinline__ float ex2(float x) {
    float y;
    asm("ex2.approx.ftz.f32 %0, %1;" : "=f"(y) : "f"(x));
    return y;
}
__device__ __forceinline__ uint32_t packh2(float lo, float hi) {
    __half2 h = __floats2half2_rn(lo, hi);
    return *reinterpret_cast<uint32_t*>(&h);
}
__device__ __forceinline__ void cp16(uint32_t saddr, const void* g) {
    asm volatile("cp.async.cg.shared.global [%0], [%1], 16;" :: "r"(saddr), "l"(g));
}
__device__ __forceinline__ void cp4(uint32_t saddr, const void* g) {
    asm volatile("cp.async.ca.shared.global [%0], [%1], 4;" :: "r"(saddr), "l"(g));
}
__device__ __forceinline__ void cp_commit() {
    asm volatile("cp.async.commit_group;");
}
template <int N>
__device__ __forceinline__ void cp_wait() {
    asm volatile("cp.async.wait_group %0;" :: "n"(N));
}
__device__ __forceinline__ void ldsm4(uint32_t& r0, uint32_t& r1, uint32_t& r2, uint32_t& r3,
                                      uint32_t addr) {
    asm volatile("ldmatrix.sync.aligned.m8n8.x4.shared.b16 {%0,%1,%2,%3}, [%4];"
                 : "=r"(r0), "=r"(r1), "=r"(r2), "=r"(r3) : "r"(addr));
}
__device__ __forceinline__ void ldsm4t(uint32_t& r0, uint32_t& r1, uint32_t& r2, uint32_t& r3,
                                       uint32_t addr) {
    asm volatile("ldmatrix.sync.aligned.m8n8.x4.trans.shared.b16 {%0,%1,%2,%3}, [%4];"
                 : "=r"(r0), "=r"(r1), "=r"(r2), "=r"(r3) : "r"(addr));
}
// D(16x8,f32) += A(16x16,f16,row) * B(16x8,f16,col)
__device__ __forceinline__ void mma_f16(float c[4],
                                        uint32_t a0, uint32_t a1, uint32_t a2, uint32_t a3,
                                        uint32_t b0, uint32_t b1) {
    asm volatile(
        "mma.sync.aligned.m16n8k16.row.col.f32.f16.f16.f32 "
        "{%0,%1,%2,%3}, {%4,%5,%6,%7}, {%8,%9}, {%0,%1,%2,%3};"
        : "+f"(c[0]), "+f"(c[1]), "+f"(c[2]), "+f"(c[3])
        : "r"(a0), "r"(a1), "r"(a2), "r"(a3), "r"(b0), "r"(b1));
}

// ---------------- fused fp32 -> fp16 conversion: all 7 tensors, ONE launch ----------------
// z==3 (Wq) is scaled by qscale = 0.125 * log2(e) so Q comes out of the QKV GEMM pre-scaled.
__global__ void f32to16_all(
    const float4* __restrict__ s0, const float4* __restrict__ s1, const float4* __restrict__ s2,
    const float4* __restrict__ s3, const float4* __restrict__ s4, const float4* __restrict__ s5,
    const float4* __restrict__ s6,
    uint4* __restrict__ d0, uint4* __restrict__ d1, uint4* __restrict__ d2,
    uint4* __restrict__ d3, uint4* __restrict__ d4, uint4* __restrict__ d5,
    uint4* __restrict__ d6,
    int nBig, int nSmall) {
    const int z = blockIdx.z;
    const float4* in;
    uint4* out;
    int n8;
    switch (z) {
        case 0: in = s0; out = d0; n8 = nBig; break;
        case 1: in = s1; out = d1; n8 = nBig; break;
        case 2: in = s2; out = d2; n8 = nBig; break;
        case 3: in = s3; out = d3; n8 = nSmall; break;
        case 4: in = s4; out = d4; n8 = nSmall; break;
        case 5: in = s5; out = d5; n8 = nSmall; break;
        default: in = s6; out = d6; n8 = nSmall; break;
    }
    const float sc = (z == 3) ? 0.125f * 1.4426950408889634f : 1.0f;
    int i = blockIdx.x * blockDim.x + threadIdx.x;
    const int stride = gridDim.x * blockDim.x;
#pragma unroll 2
    for (; i < n8; i += stride) {
        float4 v0 = in[2 * i];
        float4 v1 = in[2 * i + 1];
        uint4 o;
        o.x = packh2(v0.x * sc, v0.y * sc);
        o.y = packh2(v0.z * sc, v0.w * sc);
        o.z = packh2(v1.x * sc, v1.y * sc);
        o.w = packh2(v1.z * sc, v1.w * sc);
        out[i] = o;
    }
}

// ---------------- fp16 GEMM: C[m][n] = sum_k A[m][k] * W[n][k] (R13 proven) ----------------
#define GBM 128
#define GBN 128
#define GBKH 64
#define GSTH 72
#define GSTGH (GBM * GSTH)
#define GNS 3
#define GSMEM (2 * GNS * GSTGH * 2)           // 110592 B

__global__ __launch_bounds__(256, 2)
void gemm_h(const __half* __restrict__ A0, const __half* __restrict__ A1, const __half* __restrict__ A2,
            const __half* __restrict__ W0, const __half* __restrict__ W1, const __half* __restrict__ W2,
            float* __restrict__ C,
            __half* __restrict__ H0, __half* __restrict__ H1, __half* __restrict__ H2,
            int outHalf) {
    extern __shared__ __half hsm[];
    __half* Asm = hsm;
    __half* Bsm = hsm + GNS * GSTGH;

    const int z = blockIdx.z;
    const __half* A = (z == 0) ? A0 : (z == 1) ? A1 : A2;
    const __half* W = (z == 0) ? W0 : (z == 1) ? W1 : W2;
    __half* H = (z == 0) ? H0 : (z == 1) ? H1 : H2;

    const int m0 = blockIdx.y * GBM;
    const int n0 = blockIdx.x * GBN;
    const int tid = threadIdx.x;
    const int w = tid >> 5, lane = tid & 31;
    const int g = lane >> 2, tig = lane & 3;
    const int wm = (w >> 2) * 64;
    const int wn = (w & 3) * 32;

    const uint32_t sA = (uint32_t)__cvta_generic_to_shared(Asm);
    const uint32_t sB = (uint32_t)__cvta_generic_to_shared(Bsm);

    const int lane7 = lane & 7;
    const int a_ro = ((lane >> 3) & 1) * 8;
    const int a_kh = ((lane >> 4) & 1) * 8;
    const int b_no = ((lane >> 4) & 1) * 8;
    const int b_kh = ((lane >> 3) & 1) * 8;

    uint32_t aIdx[4];
#pragma unroll
    for (int mt = 0; mt < 4; mt++)
        aIdx[mt] = (uint32_t)(((wm + mt * 16 + a_ro + lane7) * GSTH + a_kh) * 2);
    uint32_t bIdx[2];
#pragma unroll
    for (int nb = 0; nb < 2; nb++)
        bIdx[nb] = (uint32_t)(((wn + nb * 16 + b_no + lane7) * GSTH + b_kh) * 2);

    float acc[4][4][4];
#pragma unroll
    for (int i = 0; i < 4; i++)
#pragma unroll
        for (int j = 0; j < 4; j++)
#pragma unroll
            for (int e = 0; e < 4; e++) acc[i][j][e] = 0.f;

    const int lr = tid >> 3;
    const int lc8 = (tid & 7) << 3;

    auto issue = [&](int st, int k0) {
#pragma unroll
        for (int it = 0; it < 4; it++) {
            int row = lr + it * 32;
            cp16(sA + (uint32_t)((st * GBM + row) * GSTH + lc8) * 2,
                 &A[(size_t)(m0 + row) * DDIM + k0 + lc8]);
            cp16(sB + (uint32_t)((st * GBN + row) * GSTH + lc8) * 2,
                 &W[(size_t)(n0 + row) * DDIM + k0 + lc8]);
        }
    };

    issue(0, 0); cp_commit();
    issue(1, GBKH); cp_commit();

    const int NKT = DDIM / GBKH;      // 16
    for (int kt = 0; kt < NKT; kt++) {
        if (kt < NKT - 1) cp_wait<1>(); else cp_wait<0>();
        __syncthreads();

        const int st = kt % GNS;
        const uint32_t stb = (uint32_t)(st * GSTGH * 2);

#pragma unroll
        for (int ks = 0; ks < 4; ks++) {
            const uint32_t ksB = (uint32_t)(ks * 32);
            uint32_t b[4][2];
            ldsm4(b[0][0], b[0][1], b[1][0], b[1][1], sB + stb + bIdx[0] + ksB);
            ldsm4(b[2][0], b[2][1], b[3][0], b[3][1], sB + stb + bIdx[1] + ksB);
#pragma unroll
            for (int mt = 0; mt < 4; mt++) {
                uint32_t a0, a1, a2, a3;
                ldsm4(a0, a1, a2, a3, sA + stb + aIdx[mt] + ksB);
#pragma unroll
                for (int nt = 0; nt < 4; nt++)
                    mma_f16(acc[mt][nt], a0, a1, a2, a3, b[nt][0], b[nt][1]);
            }
        }

        if (kt + 2 < NKT) {
            issue((kt + 2) % GNS, (kt + 2) * GBKH);
            cp_commit();
        }
    }

#pragma unroll
    for (int mt = 0; mt < 4; mt++) {
        int r0 = m0 + wm + mt * 16 + g;
#pragma unroll
        for (int nt = 0; nt < 4; nt++) {
            int col = n0 + wn + nt * 8 + 2 * tig;
            float v0 = acc[mt][nt][0], v1 = acc[mt][nt][1];
            float v2 = acc[mt][nt][2], v3 = acc[mt][nt][3];
            if (outHalf) {
                *reinterpret_cast<__half2*>(&H[(size_t)r0 * DDIM + col]) =
                    __floats2half2_rn(v0, v1);
                *reinterpret_cast<__half2*>(&H[(size_t)(r0 + 8) * DDIM + col]) =
                    __floats2half2_rn(v2, v3);
            } else {
                *reinterpret_cast<float2*>(&C[(size_t)r0 * DDIM + col]) = make_float2(v0, v1);
                *reinterpret_cast<float2*>(&C[(size_t)(r0 + 8) * DDIM + col]) = make_float2(v2, v3);
            }
        }
    }
}

// ---------------- flash attention: 128-row Q tile, 16 rows/warp, 2 CTAs/SM,
// ---------------- Q pre-scaled (cp.async staging, overlapped with K/V tile 0) ----------------
#define AQT 128
#define ATHR 256
#define HPH 72    // fp16 row stride (halves)
#define ASMEM ((2*64*HPH + 2*64*HPH + AQT*HPH) * 2 + 2 * 64 * 4)   // 55808 B

__global__ __launch_bounds__(ATHR, 2)
void attn_kernel(const __half* __restrict__ QH, const __half* __restrict__ KH,
                 const __half* __restrict__ VH,
                 const int* __restrict__ mask, __half* __restrict__ O) {
    extern __shared__ uint32_t smem_u[];
    __half* Kh0 = (__half*)smem_u;
    __half* Vh0 = Kh0 + 2 * 64 * HPH;
    __half* Qs  = Vh0 + 2 * 64 * HPH;              // AQT rows (Q staging, pre-scaled)
    int* msk0 = (int*)(Qs + AQT * HPH);

    const int qi = gridDim.x - 1 - blockIdx.x;     // heavy tiles first
    const int bh = blockIdx.y;
    const int b = bh / HH, h = bh % HH;

    const int tid = threadIdx.x;
    const int w = tid >> 5, lane = tid & 31;
    const int g = lane >> 2, tig = lane & 3;
    const int wrow = w * 16;                       // 16 rows per warp

    const __half* Qb = QH + ((size_t)b * SS + (size_t)qi * AQT) * DDIM + h * DKK;
    const __half* Kb = KH + (size_t)b * SS * DDIM + h * DKK;
    const __half* Vb = VH + (size_t)b * SS * DDIM + h * DKK;
    __half* Ob = O + ((size_t)b * SS + (size_t)qi * AQT) * DDIM + h * DKK;

    const uint32_t sK = (uint32_t)__cvta_generic_to_shared(Kh0);
    const uint32_t sV = (uint32_t)__cvta_generic_to_shared(Vh0);
    const uint32_t sQ = (uint32_t)__cvta_generic_to_shared(Qs);
    const uint32_t sM = (uint32_t)__cvta_generic_to_shared(msk0);

    const int lane7 = lane & 7;
    const int a_ro = ((lane >> 3) & 1) * 8;
    const int a_kh = ((lane >> 4) & 1) * 8;
    const int b_no = ((lane >> 4) & 1) * 8;
    const int b_kh = ((lane >> 3) & 1) * 8;
    const int v_ro = lane & 15;
    const int v_co = (lane >> 4) * 8;

    auto issueKV = [&](int st, int kt) {
        const __half* Kt = Kb + (size_t)kt * 64 * DDIM;
        const __half* Vt = Vb + (size_t)kt * 64 * DDIM;
#pragma unroll
        for (int t = 0; t < 2; t++) {
            int i = tid + t * ATHR;
            int r = i >> 3;
            int c8 = (i & 7) << 3;
            uint32_t off = (uint32_t)((st * 64 + r) * HPH + c8) * 2;
            cp16(sK + off, Kt + (size_t)r * DDIM + c8);
            cp16(sV + off, Vt + (size_t)r * DDIM + c8);
        }
        if (tid < 64) cp4(sM + (uint32_t)(st * 64 + tid) * 4, &mask[(size_t)b * SS + kt * 64 + tid]);
    };

    const int ktmax = 2 * qi + 1;

    // stage Q via cp.async (pre-scaled; overlaps with K/V tile 0 below)
#pragma unroll
    for (int t = 0; t < 4; t++) {
        int i = tid + t * ATHR;
        int r = i >> 3;
        int c8 = (i & 7) << 3;
        cp16(sQ + (uint32_t)(r * HPH + c8) * 2, Qb + (size_t)r * DDIM + c8);
    }
    issueKV(0, 0);
    cp_commit();

    float mrow0 = -1e30f, mrow1 = -1e30f;
    float lrow0 = 0.f, lrow1 = 0.f;
    float o[8][4];
#pragma unroll
    for (int nt = 0; nt < 8; nt++)
#pragma unroll
        for (int e = 0; e < 4; e++) o[nt][e] = 0.f;

    uint32_t qf[4][4];
    bool qloaded = false;

    const int rowmax = qi * AQT + wrow + 15;

    for (int kt = 0; kt <= ktmax; kt++) {
        const int cur = kt & 1;
        __syncthreads();
        if (kt < ktmax) {
            issueKV(cur ^ 1, kt + 1);
            cp_commit();
            cp_wait<1>();
        } else {
            cp_wait<0>();
        }
        __syncthreads();

        if (!qloaded) {   // first iteration: Q arrived with tile 0's group
            const uint32_t base = sQ + (uint32_t)(((wrow + a_ro + lane7) * HPH + a_kh) * 2);
#pragma unroll
            for (int ks = 0; ks < 4; ks++)
                ldsm4(qf[ks][0], qf[ks][1], qf[ks][2], qf[ks][3],
                      base + (uint32_t)(ks * 32));
            qloaded = true;
        }

        const uint32_t sKst = sK + (uint32_t)(cur * 64 * HPH * 2);
        const uint32_t vH0 = sV + (uint32_t)(cur * 64 * HPH * 2)
                           + (uint32_t)(v_ro * HPH + v_co) * 2;
        const int* msk = msk0 + cur * 64;

        if (kt * 64 > rowmax) continue;

        const int kbase = kt * 64;
        const int mvl0 = msk[lane], mvl1 = msk[32 + lane];
        const bool allvalid = __all_sync(0xffffffffu, (mvl0 != 0) && (mvl1 != 0));

        // S = Q @ K^T : 16x64 per warp, fp16 k16
        float s[8][4];
#pragma unroll
        for (int nt = 0; nt < 8; nt++)
            s[nt][0] = s[nt][1] = s[nt][2] = s[nt][3] = 0.f;

        const uint32_t kb0 = sKst + (uint32_t)(((b_no + lane7) * HPH + b_kh) * 2);
#pragma unroll
        for (int ks = 0; ks < 4; ks++) {
            const uint32_t ksB = (uint32_t)(ks * 32);
            uint32_t bf[8][2];
#pragma unroll
            for (int j = 0; j < 4; j++)
                ldsm4(bf[2*j][0], bf[2*j][1], bf[2*j+1][0], bf[2*j+1][1],
                      kb0 + (uint32_t)(j * 16 * HPH * 2) + ksB);
#pragma unroll
            for (int nt = 0; nt < 8; nt++)
                mma_f16(s[nt], qf[ks][0], qf[ks][1], qf[ks][2], qf[ks][3],
                        bf[nt][0], bf[nt][1]);
        }

        // masking + online softmax; P packed to fp16 registers
        const int q0 = qi * AQT + wrow + g;
        const int q1 = q0 + 8;
        const bool needc = (kbase + 63 > qi * AQT + wrow);

        if (!allvalid) {
#pragma unroll
            for (int nt = 0; nt < 8; nt++) {
                int cl = nt * 8 + 2 * tig;
                int cg = kbase + cl;
                bool mv0 = (msk[cl] != 0);
                bool mv1 = (msk[cl + 1] != 0);
                if (!mv0 || (needc && cg > q0))     s[nt][0] = -1e30f;
                if (!mv1 || (needc && cg + 1 > q0)) s[nt][1] = -1e30f;
                if (!mv0 || (needc && cg > q1))     s[nt][2] = -1e30f;
                if (!mv1 || (needc && cg + 1 > q1)) s[nt][3] = -1e30f;
            }
        } else if (needc) {
#pragma unroll
            for (int nt = 0; nt < 8; nt++) {
                int cg = kbase + nt * 8 + 2 * tig;
                if (cg > q0)     s[nt][0] = -1e30f;
                if (cg + 1 > q0) s[nt][1] = -1e30f;
                if (cg > q1)     s[nt][2] = -1e30f;
                if (cg + 1 > q1) s[nt][3] = -1e30f;
            }
        }

        float rm0 = -1e30f, rm1 = -1e30f;
#pragma unroll
        for (int nt = 0; nt < 8; nt++) {
            rm0 = fmaxf(rm0, fmaxf(s[nt][0], s[nt][1]));
            rm1 = fmaxf(rm1, fmaxf(s[nt][2], s[nt][3]));
        }
        rm0 = fmaxf(rm0, __shfl_xor_sync(0xffffffffu, rm0, 1));
        rm0 = fmaxf(rm0, __shfl_xor_sync(0xffffffffu, rm0, 2));
        rm1 = fmaxf(rm1, __shfl_xor_sync(0xffffffffu, rm1, 1));
        rm1 = fmaxf(rm1, __shfl_xor_sync(0xffffffffu, rm1, 2));

        float mn0 = fmaxf(mrow0, rm0);
        float mn1 = fmaxf(mrow1, rm1);
        float al0 = ex2(mrow0 - mn0);
        float al1 = ex2(mrow1 - mn1);
        mrow0 = mn0; mrow1 = mn1;

        uint32_t ph[8][2];
        float rs0 = 0.f, rs1 = 0.f;
#pragma unroll
        for (int nt = 0; nt < 8; nt++) {
            float p0 = ex2(s[nt][0] - mn0);
            float p1 = ex2(s[nt][1] - mn0);
            float p2 = ex2(s[nt][2] - mn1);
            float p3 = ex2(s[nt][3] - mn1);
            rs0 += p0 + p1;
            rs1 += p2 + p3;
            ph[nt][0] = packh2(p0, p1);
            ph[nt][1] = packh2(p2, p3);
        }
        rs0 += __shfl_xor_sync(0xffffffffu, rs0, 1);
        rs0 += __shfl_xor_sync(0xffffffffu, rs0, 2);
        rs1 += __shfl_xor_sync(0xffffffffu, rs1, 1);
        rs1 += __shfl_xor_sync(0xffffffffu, rs1, 2);
        lrow0 = lrow0 * al0 + rs0;
        lrow1 = lrow1 * al1 + rs1;

#pragma unroll
        for (int nt = 0; nt < 8; nt++) {
            o[nt][0] *= al0; o[nt][1] *= al0;
            o[nt][2] *= al1; o[nt][3] *= al1;
        }

        // O += P @ V, fp16 m16n8k16, P in registers, V via ldmatrix.trans
#pragma unroll
        for (int j = 0; j < 4; j++) {
            const uint32_t jb = (uint32_t)(j * 16 * HPH * 2);
            uint32_t vf[8][2];
#pragma unroll
            for (int dgi = 0; dgi < 4; dgi++)
                ldsm4t(vf[2*dgi][0], vf[2*dgi][1], vf[2*dgi+1][0], vf[2*dgi+1][1],
                       vH0 + jb + (uint32_t)(dgi * 32));
            uint32_t a0 = ph[2*j][0],   a1 = ph[2*j][1];
            uint32_t a2 = ph[2*j+1][0], a3 = ph[2*j+1][1];
#pragma unroll
            for (int nt = 0; nt < 8; nt++)
                mma_f16(o[nt], a0, a1, a2, a3, vf[nt][0], vf[nt][1]);
        }
    }

    // normalize + store as fp16 (feeds the fp16 Wo GEMM)
    {
        float i0 = 1.f / lrow0;
        float i1 = 1.f / lrow1;
        int r0 = wrow + g;
#pragma unroll
        for (int nt = 0; nt < 8; nt++) {
            int cl = nt * 8 + 2 * tig;
            *reinterpret_cast<__half2*>(&Ob[(size_t)r0 * DDIM + cl]) =
                __floats2half2_rn(o[nt][0] * i0, o[nt][1] * i0);
            *reinterpret_cast<__half2*>(&Ob[(size_t)(r0 + 8) * DDIM + cl]) =
                __floats2half2_rn(o[nt][2] * i1, o[nt][3] * i1);
        }
    }
}

// ---------------- launch ----------------
extern "C" void kernel_launch(void* const* d_in, const int* in_sizes, int n_in,
                              void* d_out, int out_size) {
    const float* xq = (const float*)d_in[0];
    const float* xk = (const float*)d_in[1];
    const float* xv = (const float*)d_in[2];
    const int* mask = (const int*)d_in[3];
    const float* Wq = (const float*)d_in[4];
    const float* Wk = (const float*)d_in[5];
    const float* Wv = (const float*)d_in[6];
    const float* Wo = (const float*)d_in[7];
    float* out = (float*)d_out;

    __half *xqh, *xkh, *xvh, *Wh, *QHp, *KHp, *VHp, *AHp;
    cudaGetSymbolAddress((void**)&xqh, g_xqh);
    cudaGetSymbolAddress((void**)&xkh, g_xkh);
    cudaGetSymbolAddress((void**)&xvh, g_xvh);
    cudaGetSymbolAddress((void**)&Wh, g_Wh);
    cudaGetSymbolAddress((void**)&QHp, g_Qh);
    cudaGetSymbolAddress((void**)&KHp, g_Kh);
    cudaGetSymbolAddress((void**)&VHp, g_Vh);
    cudaGetSymbolAddress((void**)&AHp, g_Ah);

    __half* Wqh = Wh;
    __half* Wkh = Wh + (size_t)DDIM * DDIM;
    __half* Wvh = Wh + 2 * (size_t)DDIM * DDIM;
    __half* Woh = Wh + 3 * (size_t)DDIM * DDIM;

    cudaFuncSetAttribute(gemm_h, cudaFuncAttributeMaxDynamicSharedMemorySize, GSMEM);
    cudaFuncSetAttribute(attn_kernel, cudaFuncAttributeMaxDynamicSharedMemorySize, ASMEM);

    const int NX8 = (MTOT * DDIM) / 8;   // 1048576
    const int NW8 = (DDIM * DDIM) / 8;   // 131072

    f32to16_all<<<dim3(512, 1, 7), 256>>>(
        (const float4*)xq, (const float4*)xk, (const float4*)xv,
        (const float4*)Wq, (const float4*)Wk, (const float4*)Wv, (const float4*)Wo,
        (uint4*)xqh, (uint4*)xkh, (uint4*)xvh,
        (uint4*)Wqh, (uint4*)Wkh, (uint4*)Wvh, (uint4*)Woh,
        NX8, NW8);

    // fused QKV projections (fp16 in, fp16 out; Q pre-scaled via Wq)
    gemm_h<<<dim3(DDIM / GBN, MTOT / GBM, 3), 256, GSMEM>>>(
        xqh, xkh, xvh, Wqh, Wkh, Wvh, nullptr, QHp, KHp, VHp, 1);

    attn_kernel<<<dim3(SS / AQT, BB * HH), ATHR, ASMEM>>>(QHp, KHp, VHp, mask, AHp);

    // output projection (fp16 in, fp32 out)
    gemm_h<<<dim3(DDIM / GBN, MTOT / GBM, 1), 256, GSMEM>>>(
        AHp, AHp, AHp, Woh, Woh, Woh, out, QHp, KHp, VHp, 0);
}